// round 16
// baseline (speedup 1.0000x reference)
#include <cuda_runtime.h>
#include <cuda_fp16.h>
#include <cstdint>

// Problem: H[8,4096,1024] G[8,1024,768] Wq[256,768] Wk[256,1024] -> Z[8,1024,1024]
#define B_  8
#define L_  4096
#define DH_ 1024
#define T_  1024
#define DG_ 768
#define P_  256

// ---------------------------------------------------------------------------
// PTX helpers — base-target (sm_80+): mma.sync, ldmatrix, cp.async
// ---------------------------------------------------------------------------
__device__ __forceinline__ uint32_t smem_to_u32(const void* p) {
    uint32_t a;
    asm("{ .reg .u64 t; cvta.to.shared.u64 t, %1; cvt.u32.u64 %0, t; }" : "=r"(a) : "l"(p));
    return a;
}
#define CP_ASYNC16(sa, g) \
    asm volatile("cp.async.cg.shared.global [%0], [%1], 16;" :: "r"(sa), "l"(g))
#define CP_COMMIT() asm volatile("cp.async.commit_group;")
#define CP_WAIT2()  asm volatile("cp.async.wait_group 2;")

#define LDSM_X4(r0, r1, r2, r3, addr) \
    asm volatile("ldmatrix.sync.aligned.m8n8.x4.shared.b16 {%0,%1,%2,%3}, [%4];" \
                 : "=r"(r0), "=r"(r1), "=r"(r2), "=r"(r3) : "r"(addr))
#define LDSM_X4_T(r0, r1, r2, r3, addr) \
    asm volatile("ldmatrix.sync.aligned.m8n8.x4.trans.shared.b16 {%0,%1,%2,%3}, [%4];" \
                 : "=r"(r0), "=r"(r1), "=r"(r2), "=r"(r3) : "r"(addr))

// fp16 HMMA, fp32 accumulate
__device__ __forceinline__ void mma16816h(float* d, const uint32_t* a, const uint32_t* b) {
    asm volatile(
        "mma.sync.aligned.m16n8k16.row.col.f32.f16.f16.f32 "
        "{%0,%1,%2,%3}, {%4,%5,%6,%7}, {%8,%9}, {%0,%1,%2,%3};"
        : "+f"(d[0]), "+f"(d[1]), "+f"(d[2]), "+f"(d[3])
        : "r"(a[0]), "r"(a[1]), "r"(a[2]), "r"(a[3]), "r"(b[0]), "r"(b[1]));
}

__device__ __forceinline__ uint32_t pack2h(__half a, __half b) {
    return ((uint32_t)*(uint16_t*)&b << 16) | *(uint16_t*)&a;
}

// ---------------------------------------------------------------------------
// Scratch (device globals; allocation-free)
// ---------------------------------------------------------------------------
__device__ __align__(16) __half g_Gh[(size_t)B_*T_*DG_];
__device__ __align__(16) __half g_Wqh[(size_t)P_*DG_];
__device__ __align__(16) __half g_Wkh[(size_t)P_*DH_];
__device__ __align__(16) __half g_Hh[(size_t)B_*L_*DH_];
__device__ __align__(16) __half g_Qh[(size_t)B_*T_*P_];
__device__ __align__(16) __half g_Kh[(size_t)B_*L_*P_];
__device__ __align__(16) __half g_Ph[(size_t)B_*T_*L_];
__device__ float g_sum[(size_t)B_*T_];

// ---------------------------------------------------------------------------
// Fused prep: fp32->fp16 for G, H, Wq, Wk + zero rowsums — ONE launch.
// Indexed over float4 quads.
// ---------------------------------------------------------------------------
#define NQ_G   (B_*T_*DG_/4)
#define NQ_H   (B_*L_*DH_/4)
#define NQ_WQ  (P_*DG_/4)
#define NQ_WK  (P_*DH_/4)
#define NQ_SUM (B_*T_/4)
#define NQ_TOT (NQ_G + NQ_H + NQ_WQ + NQ_WK + NQ_SUM)

__global__ __launch_bounds__(256) void prep_all(
    const float* __restrict__ G, const float* __restrict__ H,
    const float* __restrict__ Wq, const float* __restrict__ Wk,
    __half* __restrict__ Gh, __half* __restrict__ Hh,
    __half* __restrict__ Wqh, __half* __restrict__ Wkh,
    float* __restrict__ sump)
{
    int i = blockIdx.x * 256 + threadIdx.x;
    if (i >= NQ_TOT) return;
    const float* src;
    __half* dst;
    if (i < NQ_H) { src = H; dst = Hh; }
    else if ((i -= NQ_H) < NQ_G) { src = G; dst = Gh; }
    else if ((i -= NQ_G) < NQ_WQ) { src = Wq; dst = Wqh; }
    else if ((i -= NQ_WQ) < NQ_WK) { src = Wk; dst = Wkh; }
    else {
        ((float4*)sump)[i - NQ_WK] = make_float4(0.f, 0.f, 0.f, 0.f);
        return;
    }
    float4 v = ((const float4*)src)[i];
    ((uint2*)dst)[i] = make_uint2(
        pack2h(__float2half_rn(v.x), __float2half_rn(v.y)),
        pack2h(__float2half_rn(v.z), __float2half_rn(v.w)));
}

// ---------------------------------------------------------------------------
// fp16 1-term NT GEMM:  C[M,N] = A[M,K] * B[N,K]^T
// BM=BN=128, BK=32, 8 warps (2M x 4N), 3-stage cp.async, 2 CTAs/SM.
// EPI 0: Ch = half(acc)                     (Q/K projections)
// EPI 1: ph = half(exp(acc*scale)); Ch = ph; row sums over ROUNDED ph  (S)
// ---------------------------------------------------------------------------
#define AROWB  80
#define TILEB  (128 * AROWB)        // 10240 B per operand tile
#define T1_STAGE (2 * TILEB)        // A, B = 20480
#define T1_SMEM  (3 * T1_STAGE)     // 61440 (x2 CTA = 122880 <= 228K)

template<int EPI>
__global__ __launch_bounds__(256, 2) void gemm_1t(
    const __half* __restrict__ A, const __half* __restrict__ Bq,
    __half* __restrict__ Ch, float* __restrict__ rowsums,
    int N, int K, long sA, long sB, long sC, long sRS, float scale)
{
    extern __shared__ char smem[];
    const uint32_t sb = smem_to_u32(smem);
    const int tid  = threadIdx.x, wid = tid >> 5, lane = tid & 31;
    const int row0 = blockIdx.y * 128;
    const int col0 = blockIdx.x * 128;
    const long zb  = blockIdx.z;
    const int wm = (wid >> 2) * 64;
    const int wn = (wid & 3) * 32;

    const char* gA = (const char*)(A  + zb * sA + (long)row0 * K);
    const char* gB = (const char*)(Bq + zb * sB + (long)col0 * K);
    const long ld = (long)K * 2;

    const int r_  = tid >> 2;
    const int cb_ = (tid & 3) * 16;
    const int NC  = K >> 5;

    auto load_stage = [&](int c) {
        const uint32_t s0 = sb + (uint32_t)((c % 3) * T1_STAGE);
        const long kb = (long)c * 64;
#pragma unroll
        for (int i = 0; i < 2; i++) {
            const int row = r_ + i * 64;
            CP_ASYNC16(s0 + (uint32_t)(row * AROWB + cb_), gA + kb + (long)row * ld + cb_);
            CP_ASYNC16(s0 + (uint32_t)(TILEB + row * AROWB + cb_),
                       gB + kb + (long)row * ld + cb_);
        }
    };

    float acc[4][4][4];
#pragma unroll
    for (int a = 0; a < 4; a++)
#pragma unroll
        for (int b = 0; b < 4; b++)
#pragma unroll
            for (int q = 0; q < 4; q++) acc[a][b][q] = 0.f;

    load_stage(0); CP_COMMIT();
    load_stage(1); CP_COMMIT();
    load_stage(2); CP_COMMIT();

    const int aro = (wm + ((lane >> 3) & 1) * 8 + (lane & 7)) * AROWB + (lane >> 4) * 16;
    const int bro = (wn + (lane >> 4) * 8 + (lane & 7)) * AROWB + ((lane >> 3) & 1) * 16;

    for (int c = 0; c < NC; c++) {
        CP_WAIT2();
        __syncthreads();
        const uint32_t s0 = sb + (uint32_t)((c % 3) * T1_STAGE);

#pragma unroll
        for (int k16 = 0; k16 < 2; k16++) {
            const int kb = k16 * 32;
            uint32_t a_[4][4], bh[4][2];
#pragma unroll
            for (int mt = 0; mt < 4; mt++)
                LDSM_X4(a_[mt][0], a_[mt][1], a_[mt][2], a_[mt][3],
                        s0 + (uint32_t)(aro + mt * (16 * AROWB) + kb));
#pragma unroll
            for (int p = 0; p < 2; p++)
                LDSM_X4(bh[2*p][0], bh[2*p][1], bh[2*p+1][0], bh[2*p+1][1],
                        s0 + (uint32_t)(TILEB + bro + p * (16 * AROWB) + kb));
#pragma unroll
            for (int mt = 0; mt < 4; mt++)
#pragma unroll
                for (int nt = 0; nt < 4; nt++)
                    mma16816h(acc[mt][nt], a_[mt], bh[nt]);
        }
        __syncthreads();
        if (c + 3 < NC) load_stage(c + 3);
        CP_COMMIT();
    }

    // ---- epilogue ----
    float* rowsum = (float*)smem;
    if (EPI == 1) {
        __syncthreads();
        if (tid < 128) rowsum[tid] = 0.f;
        __syncthreads();
    }

#pragma unroll
    for (int mt = 0; mt < 4; mt++) {
        const int rl0 = wm + mt * 16 + (lane >> 2);
        const int rg0 = row0 + rl0;
        float s0a = 0.f, s1a = 0.f;
#pragma unroll
        for (int nt = 0; nt < 4; nt++) {
            const int cg = col0 + wn + nt * 8 + (lane & 3) * 2;
            const float* d = acc[mt][nt];
            const long o0 = zb * sC + (long)rg0 * N + cg;
            const long o1 = o0 + 8L * N;
            if (EPI == 1) {
                __half p0 = __float2half_rn(__expf(d[0] * scale));
                __half p1 = __float2half_rn(__expf(d[1] * scale));
                __half p2 = __float2half_rn(__expf(d[2] * scale));
                __half p3 = __float2half_rn(__expf(d[3] * scale));
                s0a += __half2float(p0) + __half2float(p1);
                s1a += __half2float(p2) + __half2float(p3);
                *(uint32_t*)(Ch + o0) = pack2h(p0, p1);
                *(uint32_t*)(Ch + o1) = pack2h(p2, p3);
            } else {
                *(uint32_t*)(Ch + o0) = pack2h(__float2half_rn(d[0]), __float2half_rn(d[1]));
                *(uint32_t*)(Ch + o1) = pack2h(__float2half_rn(d[2]), __float2half_rn(d[3]));
            }
        }
        if (EPI == 1) {
            s0a += __shfl_xor_sync(0xffffffffu, s0a, 1);
            s0a += __shfl_xor_sync(0xffffffffu, s0a, 2);
            s1a += __shfl_xor_sync(0xffffffffu, s1a, 1);
            s1a += __shfl_xor_sync(0xffffffffu, s1a, 2);
            if ((lane & 3) == 0) {
                atomicAdd(&rowsum[rl0],     s0a);
                atomicAdd(&rowsum[rl0 + 8], s1a);
            }
        }
    }
    if (EPI == 1) {
        __syncthreads();
        if (tid < 128)
            atomicAdd(&rowsums[zb * sRS + row0 + tid], rowsum[tid]);
    }
}

// ---------------------------------------------------------------------------
// PV GEMM (fp16 1-term, NN trans-B):
// Z[t,d] = (Σ_l Ph[t,l] * Hh[l,d]) / (s[t]+eps),  s = Σ_l Ph[t,l]
// BM=BN=128, BK=32, 8 warps, 3-stage cp.async, 2 CTAs/SM.
// ---------------------------------------------------------------------------
#define BROWB   272
#define BTILEB  (32 * BROWB)                 // 8704 B
#define PV_STAGE (TILEB + BTILEB)            // 18944
#define PV_SMEM  (3 * PV_STAGE)              // 56832 (x2 CTA = 113664)

__global__ __launch_bounds__(256, 2) void gemm_pv1(
    const __half* __restrict__ Ah, const __half* __restrict__ Bq,
    float* __restrict__ C, const float* __restrict__ rowdiv,
    int N, int K, long sA, long sB, long sC, long sDiv)
{
    extern __shared__ char smem[];
    const uint32_t sb = smem_to_u32(smem);
    const int tid  = threadIdx.x, wid = tid >> 5, lane = tid & 31;
    const int row0 = blockIdx.y * 128;
    const int col0 = blockIdx.x * 128;
    const long zb  = blockIdx.z;
    const int wm = (wid >> 2) * 64;
    const int wn = (wid & 3) * 32;

    const char* gAh = (const char*)(Ah + zb * sA + (long)row0 * K);
    const char* gB  = (const char*)(Bq + zb * sB + col0);
    const long ldA = (long)K * 2;
    const long ldB = (long)DH_ * 2;

    const int NC = K >> 5;

    const int ar_  = tid >> 2;
    const int acb_ = (tid & 3) * 16;
    const int br_  = tid >> 4;         // 0..15
    const int bcb_ = (tid & 15) * 16;  // 0..240

    auto load_stage = [&](int c) {
        const uint32_t s0 = sb + (uint32_t)((c % 3) * PV_STAGE);
        const long kbA = (long)c * 64;
        const long krB = (long)c * 32;
#pragma unroll
        for (int i = 0; i < 2; i++) {
            const int row = ar_ + i * 64;
            CP_ASYNC16(s0 + (uint32_t)(row * AROWB + acb_),
                       gAh + kbA + (long)row * ldA + acb_);
        }
#pragma unroll
        for (int i = 0; i < 2; i++) {
            const int krow = br_ + i * 16;
            CP_ASYNC16(s0 + (uint32_t)(TILEB + krow * BROWB + bcb_),
                       gB + (krB + krow) * ldB + bcb_);
        }
    };

    float acc[4][4][4];
#pragma unroll
    for (int a = 0; a < 4; a++)
#pragma unroll
        for (int b = 0; b < 4; b++)
#pragma unroll
            for (int q = 0; q < 4; q++) acc[a][b][q] = 0.f;

    load_stage(0); CP_COMMIT();
    load_stage(1); CP_COMMIT();
    load_stage(2); CP_COMMIT();

    const int aro = (wm + ((lane >> 3) & 1) * 8 + (lane & 7)) * AROWB + (lane >> 4) * 16;
    const int btm = lane >> 3;
    const int bkr = (lane & 7) + (btm & 1) * 8;
    const int bco = (wn + (btm >> 1) * 8) * 2;

    for (int c = 0; c < NC; c++) {
        CP_WAIT2();
        __syncthreads();
        const uint32_t s0 = sb + (uint32_t)((c % 3) * PV_STAGE);

#pragma unroll
        for (int k16 = 0; k16 < 2; k16++) {
            const int kbA = k16 * 32;
            uint32_t a_[4][4], bh[4][2];
#pragma unroll
            for (int mt = 0; mt < 4; mt++)
                LDSM_X4(a_[mt][0], a_[mt][1], a_[mt][2], a_[mt][3],
                        s0 + (uint32_t)(aro + mt * (16 * AROWB) + kbA));
            const uint32_t bbase = s0 + (uint32_t)(TILEB + (k16 * 16 + bkr) * BROWB + bco);
#pragma unroll
            for (int p = 0; p < 2; p++)
                LDSM_X4_T(bh[2*p][0], bh[2*p][1], bh[2*p+1][0], bh[2*p+1][1],
                          bbase + (uint32_t)(p * 32));
#pragma unroll
            for (int mt = 0; mt < 4; mt++)
#pragma unroll
                for (int nt = 0; nt < 4; nt++)
                    mma16816h(acc[mt][nt], a_[mt], bh[nt]);
        }
        __syncthreads();
        if (c + 3 < NC) load_stage(c + 3);
        CP_COMMIT();
    }

    // ---- epilogue: divide by row sum ----
#pragma unroll
    for (int mt = 0; mt < 4; mt++) {
        const int rg0 = row0 + wm + mt * 16 + (lane >> 2);
        const int rg1 = rg0 + 8;
        const float m0 = 1.f / (rowdiv[zb * sDiv + rg0] + 1e-8f);
        const float m1 = 1.f / (rowdiv[zb * sDiv + rg1] + 1e-8f);
#pragma unroll
        for (int nt = 0; nt < 4; nt++) {
            const int cg = col0 + wn + nt * 8 + (lane & 3) * 2;
            const float* d = acc[mt][nt];
            *(float2*)(C + zb * sC + (long)rg0 * N + cg) = make_float2(d[0]*m0, d[1]*m0);
            *(float2*)(C + zb * sC + (long)rg1 * N + cg) = make_float2(d[2]*m1, d[3]*m1);
        }
    }
}

// ---------------------------------------------------------------------------
extern "C" void kernel_launch(void* const* d_in, const int* in_sizes, int n_in,
                              void* d_out, int out_size)
{
    const float* H  = (const float*)d_in[0];
    const float* G  = (const float*)d_in[1];
    const float* Wq = (const float*)d_in[2];
    const float* Wk = (const float*)d_in[3];
    float* Z = (float*)d_out;

    __half *Gh,*Wqh,*Wkh,*Hh,*Qh,*Kh,*Ph;
    float *sump;
    cudaGetSymbolAddress((void**)&Gh,  g_Gh);
    cudaGetSymbolAddress((void**)&Wqh, g_Wqh);
    cudaGetSymbolAddress((void**)&Wkh, g_Wkh);
    cudaGetSymbolAddress((void**)&Hh,  g_Hh);
    cudaGetSymbolAddress((void**)&Qh,  g_Qh);
    cudaGetSymbolAddress((void**)&Kh,  g_Kh);
    cudaGetSymbolAddress((void**)&Ph,  g_Ph);
    cudaGetSymbolAddress((void**)&sump,g_sum);

    cudaFuncSetAttribute(gemm_1t<0>, cudaFuncAttributeMaxDynamicSharedMemorySize, T1_SMEM);
    cudaFuncSetAttribute(gemm_1t<1>, cudaFuncAttributeMaxDynamicSharedMemorySize, T1_SMEM);
    cudaFuncSetAttribute(gemm_pv1,   cudaFuncAttributeMaxDynamicSharedMemorySize, PV_SMEM);

    // 1) fused prep: all fp16 conversions + zero row sums (single launch)
    prep_all<<<(NQ_TOT + 255) / 256, 256>>>(G, H, Wq, Wk, Gh, Hh, Wqh, Wkh, sump);

    // 2) Q = half(Gh Wqh^T)  [8192,256]
    gemm_1t<0><<<dim3(P_/128, (B_*T_)/128, 1), 256, T1_SMEM>>>(
        Gh, Wqh, Qh, nullptr, P_, DG_, 0, 0, 0, 0, 1.f);

    // 3) K = half(Hh Wkh^T)  [32768,256]
    gemm_1t<0><<<dim3(P_/128, (B_*L_)/128, 1), 256, T1_SMEM>>>(
        Hh, Wkh, Kh, nullptr, P_, DH_, 0, 0, 0, 0, 1.f);

    // 4) Ph = half(exp((Qh Kh^T)/16)) + consistent row sums
    gemm_1t<1><<<dim3(L_/128, T_/128, B_), 256, T1_SMEM>>>(
        Qh, Kh, Ph, sump,
        L_, P_, (long)T_*P_, (long)L_*P_, (long)T_*L_, T_, 0.0625f);

    // 5) Z = (Ph * Hh) / (s+eps)   (NN, trans-B reads Hh directly)
    gemm_pv1<<<dim3(DH_/128, T_/128, B_), 256, PV_SMEM>>>(
        Ph, Hh, Z, sump,
        DH_, L_, (long)T_*L_, (long)L_*DH_, (long)T_*DH_, T_);
}